// round 4
// baseline (speedup 1.0000x reference)
#include <cuda_runtime.h>
#include <stdint.h>

#define DW    32     // D_WORLDS
#define K2D   64     // 2*D_WORLDS
#define NW    512    // N_WORLDS
#define BATCH 2048

// Packed dual-fp32 FMA (sm_100+ PTX-only), accumulate in place
#define FMA2(acc_, a_, b_) \
    asm("fma.rn.f32x2 %0, %1, %2, %0;" : "+l"(acc_) : "l"(a_), "l"(b_))

// One k-pair (rows k, k+1) against this thread's 8 d's / 8 cols.
// x0a,x0b = row k (cols lo/hi), x1a,x1b = row k+1. wk -> &ws2[d0*K2D + k].
__device__ __forceinline__ void proc_kpair(uint64_t acc[8][4],
                                           const ulonglong2 x0a, const ulonglong2 x0b,
                                           const ulonglong2 x1a, const ulonglong2 x1b,
                                           const float2* __restrict__ wk) {
    #pragma unroll
    for (int dd = 0; dd < 8; dd++) {
        // Broadcast LDS.128: {dup w[d][k], dup w[d][k+1]}
        ulonglong2 wv = *(const ulonglong2*)(wk + (size_t)dd * K2D);
        FMA2(acc[dd][0], wv.x, x0a.x);
        FMA2(acc[dd][1], wv.x, x0a.y);
        FMA2(acc[dd][2], wv.x, x0b.x);
        FMA2(acc[dd][3], wv.x, x0b.y);
        FMA2(acc[dd][0], wv.y, x1a.x);
        FMA2(acc[dd][1], wv.y, x1a.y);
        FMA2(acc[dd][2], wv.y, x1b.x);
        FMA2(acc[dd][3], wv.y, x1b.y);
    }
}

__global__ __launch_bounds__(256, 2)
void binop_fused_kernel(const float* __restrict__ states,   // [8*2048, 32, 512]
                        const float* __restrict__ W,        // [128, 32, 64]
                        const float* __restrict__ b,        // [128, 32]
                        const int*   __restrict__ indices,  // [2048]
                        const int*   __restrict__ symbols,  // [2048]
                        const int*   __restrict__ args,     // [2048, 2]
                        float*       __restrict__ out)      // [2048, 32, 512]
{
    __shared__ __align__(16) float2 ws2[DW * K2D];   // dup'd W[sym], 16 KB
    __shared__ float bsh[DW];
    __shared__ float sqp[4][64][8];                  // per-group partial sq sums, 8 KB

    const int n  = blockIdx.x;
    const int t  = threadIdx.x;
    const int tg = t >> 6;        // d-group: d = 8*tg .. 8*tg+7
    const int cl = t & 63;        // owns world cols 8*cl .. 8*cl+7
    const int d0 = tg * 8;

    const int idx = indices[n];
    const int sym = symbols[n];
    const int a0  = args[2 * n];
    const int a1  = args[2 * n + 1];

    // Load + duplicate W[sym] into smem
    const float* Wp = W + (size_t)sym * (DW * K2D);
    #pragma unroll
    for (int i = 0; i < 8; i++) {
        int j = t + 256 * i;
        float v = Wp[j];
        ws2[j] = make_float2(v, v);
    }
    if (t < DW) bsh[t] = b[sym * DW + t];
    __syncthreads();

    // ulonglong2 view of x rows: row kk at +kk*128 units; this thread at +2*cl.
    // kk 0..31 -> left state, 32..63 -> right state (pre-biased by -32 rows).
    const ulonglong2* bl  = (const ulonglong2*)(states + (size_t)(a0 * BATCH + idx) * (DW * NW)) + 2 * cl;
    const ulonglong2* br2 = (const ulonglong2*)(states + (size_t)(a1 * BATCH + idx) * (DW * NW)) + 2 * cl
                            - 32 * 128;

    // acc[dd][p]: packed col-pair p (of 4) for d = d0+dd, init to bias
    uint64_t acc[8][4];
    #pragma unroll
    for (int dd = 0; dd < 8; dd++) {
        float bv = bsh[d0 + dd];
        uint64_t pb;
        asm("mov.b64 %0, {%1,%2};" : "=l"(pb) : "f"(bv), "f"(bv));
        acc[dd][0] = pb; acc[dd][1] = pb; acc[dd][2] = pb; acc[dd][3] = pb;
    }

    const float2* wbase = ws2 + d0 * K2D;

    // Double-buffered k-pair loop (32 k-pairs; A/B = 2 rows x 2 ull2 each)
    ulonglong2 A0, A1, A2, A3, B0, B1, B2, B3;
    {
        const ulonglong2* p = bl;            // kk = 0,1
        A0 = p[0];   A1 = p[1];
        A2 = p[128]; A3 = p[129];
    }

    #pragma unroll 1
    for (int kq = 0; kq < 32; kq += 2) {
        {   // prefetch k-pair kq+1 (rows 2kq+2, 2kq+3)
            const int kk = 2 * kq + 2;
            const ulonglong2* p = ((kk < 32) ? bl : br2) + kk * 128;
            B0 = p[0];   B1 = p[1];
            B2 = p[128]; B3 = p[129];
        }
        proc_kpair(acc, A0, A1, A2, A3, wbase + 2 * kq);

        {   // prefetch k-pair kq+2 (clamped: last iter redundantly reloads 60,61)
            const int kk2 = (kq + 2 < 32) ? (4 * ((kq + 2) >> 1)) : 60;
            const int kk = (kq + 2 < 32) ? (2 * kq + 4) : 60;
            (void)kk2;
            const ulonglong2* p = ((kk < 32) ? bl : br2) + kk * 128;
            A0 = p[0];   A1 = p[1];
            A2 = p[128]; A3 = p[129];
        }
        proc_kpair(acc, B0, B1, B2, B3, wbase + 2 * kq + 2);
    }

    // Partial squared sums over this thread's 8 d's, per column
    float sq[8];
    #pragma unroll
    for (int j = 0; j < 8; j++) sq[j] = 0.f;
    #pragma unroll
    for (int dd = 0; dd < 8; dd++) {
        #pragma unroll
        for (int p = 0; p < 4; p++) {
            float2 v = *(float2*)&acc[dd][p];
            sq[2 * p]     = fmaf(v.x, v.x, sq[2 * p]);
            sq[2 * p + 1] = fmaf(v.y, v.y, sq[2 * p + 1]);
        }
    }
    #pragma unroll
    for (int j = 0; j < 8; j++) sqp[tg][cl][j] = sq[j];
    __syncthreads();

    float s[8];
    #pragma unroll
    for (int j = 0; j < 8; j++) {
        float tot = sqp[0][cl][j] + sqp[1][cl][j] + sqp[2][cl][j] + sqp[3][cl][j];
        s[j] = rsqrtf(fmaxf(tot, 1e-12f));
    }

    // Scatter row = indices[n] (arange -> bijective, plain stores)
    ulonglong2* op = (ulonglong2*)(out + (size_t)idx * (DW * NW)) + 2 * cl;
    #pragma unroll
    for (int dd = 0; dd < 8; dd++) {
        float2 v0 = *(float2*)&acc[dd][0];
        float2 v1 = *(float2*)&acc[dd][1];
        float2 v2 = *(float2*)&acc[dd][2];
        float2 v3 = *(float2*)&acc[dd][3];
        float4 r0 = make_float4(v0.x * s[0], v0.y * s[1], v1.x * s[2], v1.y * s[3]);
        float4 r1 = make_float4(v2.x * s[4], v2.y * s[5], v3.x * s[6], v3.y * s[7]);
        op[(size_t)(d0 + dd) * 128]     = *(ulonglong2*)&r0;
        op[(size_t)(d0 + dd) * 128 + 1] = *(ulonglong2*)&r1;
    }
}

extern "C" void kernel_launch(void* const* d_in, const int* in_sizes, int n_in,
                              void* d_out, int out_size) {
    const float* states  = (const float*)d_in[0];
    const float* W       = (const float*)d_in[1];
    const float* b       = (const float*)d_in[2];
    const int*   indices = (const int*)d_in[3];
    const int*   symbols = (const int*)d_in[4];
    const int*   args    = (const int*)d_in[5];
    float*       out     = (float*)d_out;

    binop_fused_kernel<<<BATCH, 256>>>(states, W, b, indices, symbols, args, out);
}